// round 15
// baseline (speedup 1.0000x reference)
#include <cuda_runtime.h>
#include <cuda_fp16.h>
#include <cstdint>
#include <math.h>

#define NROWS 16384
#define DDIM  256
#define INV_TEMP 14.285714285714286f
#define KCA 20.609640474436812f   /* (1/0.07)*log2(e) */
#define LN2 0.6931471805599453f

#define BM 256
#define BN 128
#define BK 32
#define STG_BYTES 24576           /* (256+128) rows x 64B */
#define NSTAGE 4
#define SMEM_TOTAL (NSTAGE * STG_BYTES)   /* 96 KB */

// ---------------------------------------------------------------------------
// Scratch (no allocations allowed)
// ---------------------------------------------------------------------------
__device__ __half g_qn[NROWS * DDIM];
__device__ __half g_kn[NROWS * DDIM];
__device__ float g_S[NROWS];
__device__ float g_diag[NROWS];

// ---------------------------------------------------------------------------
// PTX helpers (base ISA only: compiles at target sm_103)
// ---------------------------------------------------------------------------
__device__ __forceinline__ uint32_t smem_u32(const void* p) {
    uint32_t a;
    asm("{ .reg .u64 t; cvta.to.shared.u64 t, %1; cvt.u32.u64 %0, t; }" : "=r"(a) : "l"(p));
    return a;
}
__device__ __forceinline__ void ldsm_x4(uint32_t* r, uint32_t addr) {
    asm volatile("ldmatrix.sync.aligned.m8n8.x4.shared.b16 {%0,%1,%2,%3}, [%4];"
                 : "=r"(r[0]), "=r"(r[1]), "=r"(r[2]), "=r"(r[3]) : "r"(addr));
}
// fp16-accumulate HMMA: D(2xb32 packed half2) = A(4) * B(2) + D
__device__ __forceinline__ void mma_16816_f16(uint32_t* d, const uint32_t* a, const uint32_t* b) {
    asm volatile("mma.sync.aligned.m16n8k16.row.col.f16.f16.f16.f16 "
                 "{%0,%1}, {%2,%3,%4,%5}, {%6,%7}, {%0,%1};"
                 : "+r"(d[0]), "+r"(d[1])
                 : "r"(a[0]), "r"(a[1]), "r"(a[2]), "r"(a[3]), "r"(b[0]), "r"(b[1]));
}
#define CP_ASYNC16(dst, src) \
    asm volatile("cp.async.cg.shared.global [%0], [%1], 16;" :: "r"(dst), "l"(src) : "memory")
#define CP_COMMIT() asm volatile("cp.async.commit_group;" ::: "memory")
#define CP_WAIT2()  asm volatile("cp.async.wait_group 2;" ::: "memory")

// Fast exp2 on the FMA/ALU pipes (avoids MUFU rt=8). x in [-42, 0.3] here.
__device__ __forceinline__ float fast_exp2(float x) {
    float r = x + 12582912.0f;
    float n = r - 12582912.0f;
    float f = x - n;
    int   e = __float_as_int(r) - 0x4B400000;
    float p = fmaf(f, 0.0096181291f, 0.0555041086f);
    p = fmaf(f, p, 0.2402265069f);
    p = fmaf(f, p, 0.6931471806f);
    p = fmaf(f, p, 1.0f);
    return p * __int_as_float((127 + e) << 23);
}

// Fast natural log on FMA/ALU pipes (S_i values here are modest positives).
__device__ __forceinline__ float fast_log(float x) {
    int   xi = __float_as_int(x);
    int   e  = ((xi - 0x3F2AAAAB) >> 23);            // exponent rel. to 2/3
    float m  = __int_as_float(xi - (e << 23));       // in [2/3, 4/3)
    float t  = (m - 1.0f) / (m + 1.0f);              // |t| <= 0.2
    float t2 = t * t;
    float p  = fmaf(t2, 0.1133157f, 0.1332887f);
    p = fmaf(t2, p, 0.2000003f);
    p = fmaf(t2, p, 0.3333333f);
    float lnm = t * fmaf(t2, p * 2.0f, 2.0f);
    return fmaf((float)e, LN2, lnm);
}

// ---------------------------------------------------------------------------
// Kernel 1: L2 normalize fp32 -> fp16. Two rows per warp; zeroes g_S.
// ---------------------------------------------------------------------------
__global__ void normalize_kernel(const float* __restrict__ q,
                                 const float* __restrict__ k) {
    int warp = threadIdx.x >> 5;
    int lane = threadIdx.x & 31;
    int row0 = (blockIdx.x * (blockDim.x >> 5) + warp) * 2;
    if (row0 >= NROWS) return;

    const float* src = (blockIdx.y == 0) ? q : k;
    __half*      dst = (blockIdx.y == 0) ? g_qn : g_kn;

    const float4* a4 = reinterpret_cast<const float4*>(src + (size_t)row0 * DDIM);
    const float4* b4 = reinterpret_cast<const float4*>(src + (size_t)(row0 + 1) * DDIM);
    float4 a0 = a4[2 * lane], a1 = a4[2 * lane + 1];
    float4 b0 = b4[2 * lane], b1 = b4[2 * lane + 1];

    float sa = a0.x * a0.x + a0.y * a0.y + a0.z * a0.z + a0.w * a0.w
             + a1.x * a1.x + a1.y * a1.y + a1.z * a1.z + a1.w * a1.w;
    float sb = b0.x * b0.x + b0.y * b0.y + b0.z * b0.z + b0.w * b0.w
             + b1.x * b1.x + b1.y * b1.y + b1.z * b1.z + b1.w * b1.w;
#pragma unroll
    for (int o = 16; o; o >>= 1) {
        sa += __shfl_xor_sync(0xffffffffu, sa, o);
        sb += __shfl_xor_sync(0xffffffffu, sb, o);
    }
    float ia = 1.0f / fmaxf(sqrtf(sa), 1e-12f);
    float ib = 1.0f / fmaxf(sqrtf(sb), 1e-12f);

    __half2 h[4];
    h[0] = __floats2half2_rn(a0.x * ia, a0.y * ia);
    h[1] = __floats2half2_rn(a0.z * ia, a0.w * ia);
    h[2] = __floats2half2_rn(a1.x * ia, a1.y * ia);
    h[3] = __floats2half2_rn(a1.z * ia, a1.w * ia);
    *reinterpret_cast<uint4*>(dst + (size_t)row0 * DDIM + lane * 8) =
        *reinterpret_cast<uint4*>(h);
    h[0] = __floats2half2_rn(b0.x * ib, b0.y * ib);
    h[1] = __floats2half2_rn(b0.z * ib, b0.w * ib);
    h[2] = __floats2half2_rn(b1.x * ib, b1.y * ib);
    h[3] = __floats2half2_rn(b1.z * ib, b1.w * ib);
    *reinterpret_cast<uint4*>(dst + (size_t)(row0 + 1) * DDIM + lane * 8) =
        *reinterpret_cast<uint4*>(h);

    if (blockIdx.y == 0 && lane < 2) g_S[row0 + lane] = 0.0f;
}

// ---------------------------------------------------------------------------
// Kernel 2: fp16 mma.sync GEMM (qn @ kn^T) fused with exp-sum epilogue.
// CTA tile 256x128, 256 threads, 8 warps (4m x 2n) each 64x64 with fp16
// packed-half2 accumulators (64 regs) -> 16 warps/SM at occ 2 (4/SMSP) for
// latency hiding, with R12's best-in-class issue economy. BK=32, 4 stages
// (64B rows, swizzle chunk^=(r>>1)&3; k-slice 1 address = slice 0 XOR 32).
// ---------------------------------------------------------------------------
__global__ void __launch_bounds__(256, 2) gemm_lse_mma() {
    extern __shared__ __align__(1024) char smem[];
    const uint32_t sb = smem_u32(smem);

    const int tid  = threadIdx.x;
    const int lane = tid & 31;
    const int wid  = tid >> 5;
    const int wm   = wid >> 1;      // 0..3 -> 64-row slice
    const int wn   = wid & 1;       // 0..1 -> 64-col slice
    const int bx   = blockIdx.x;    // col tile (BN=128)
    const int by   = blockIdx.y;    // row tile (BM=256)
    const int rowBase = by * BM;
    const int colBase = bx * BN;

    // --- swizzled ldmatrix offsets for k-slice 0 (slice 1: XOR 32) ---
    uint32_t offA[4], offB[4];
#pragma unroll
    for (int mi = 0; mi < 4; mi++) {
        int r = wm * 64 + mi * 16 + (lane & 15);
        int c = lane >> 4;                       // 0..1
        offA[mi] = r * 64 + ((c ^ ((r >> 1) & 3)) << 4);
    }
#pragma unroll
    for (int ni = 0; ni < 4; ni++) {
        int r = BM + wn * 64 + ni * 16 + (lane & 7) + ((lane >> 4) << 3);
        int c = (lane >> 3) & 1;                 // 0..1
        offB[ni] = r * 64 + ((c ^ ((r >> 1) & 3)) << 4);
    }

    // --- stage loader: 6 x 16B chunks per thread (384 rows x 4 chunks) ---
    auto load_stage = [&](int kb, int s) {
#pragma unroll
        for (int h = 0; h < 6; h++) {
            int j = tid + h * 256;          // 0..1535
            int r = j >> 2, c = j & 3;
            uint32_t dst = sb + s * STG_BYTES + r * 64 + ((c ^ ((r >> 1) & 3)) << 4);
            const __half* src = (r < BM)
                ? g_qn + (size_t)(rowBase + r) * DDIM + kb * BK + c * 8
                : g_kn + (size_t)(colBase + (r - BM)) * DDIM + kb * BK + c * 8;
            CP_ASYNC16(dst, src);
        }
        CP_COMMIT();
    };

    uint32_t acc[4][8][2];          // packed half2: [mi][ni8][row-group]
#pragma unroll
    for (int mi = 0; mi < 4; mi++)
#pragma unroll
        for (int ni = 0; ni < 8; ni++) { acc[mi][ni][0] = 0u; acc[mi][ni][1] = 0u; }

    load_stage(0, 0);
    load_stage(1, 1);
    load_stage(2, 2);

#pragma unroll
    for (int kb = 0; kb < 8; kb++) {
        CP_WAIT2();
        __syncthreads();                    // stage kb ready; kb-1 reads done
        if (kb + 3 < 8) load_stage(kb + 3, (kb + 3) & 3);
        else            CP_COMMIT();        // keep wait_group count exact

        const uint32_t stg = sb + (kb & 3) * STG_BYTES;
#pragma unroll
        for (int s = 0; s < 2; s++) {       // 2 barrier-free k16 slices
            const uint32_t kx = (uint32_t)(s << 5);
            uint32_t af[4][4], bf[4][4];
#pragma unroll
            for (int mi = 0; mi < 4; mi++) ldsm_x4(af[mi], (stg + offA[mi]) ^ kx);
#pragma unroll
            for (int ni = 0; ni < 4; ni++) ldsm_x4(bf[ni], (stg + offB[ni]) ^ kx);
#pragma unroll
            for (int mi = 0; mi < 4; mi++)
#pragma unroll
                for (int ni = 0; ni < 4; ni++) {
                    mma_16816_f16(acc[mi][ni * 2 + 0], af[mi], &bf[ni][0]);
                    mma_16816_f16(acc[mi][ni * 2 + 1], af[mi], &bf[ni][2]);
                }
        }
    }

    // --- fused epilogue: exp2 row-sums + diag capture ---
    float rs[4][2];
#pragma unroll
    for (int mi = 0; mi < 4; mi++) { rs[mi][0] = 0.0f; rs[mi][1] = 0.0f; }
    const bool diagblk = ((bx >> 1) == by);
#pragma unroll
    for (int mi = 0; mi < 4; mi++)
#pragma unroll
        for (int ni = 0; ni < 8; ni++)
#pragma unroll
            for (int g = 0; g < 2; g++) {
                float2 f = __half22float2(*reinterpret_cast<__half2*>(&acc[mi][ni][g]));
                rs[mi][g] += fast_exp2(fmaf(f.x, KCA, -KCA));
                rs[mi][g] += fast_exp2(fmaf(f.y, KCA, -KCA));
                if (diagblk) {
                    int grow = rowBase + wm * 64 + mi * 16 + g * 8 + (lane >> 2);
                    int gcol = colBase + wn * 64 + ni * 8 + ((lane & 3) << 1);
                    if (grow == gcol)     g_diag[grow] = f.x * INV_TEMP;
                    if (grow == gcol + 1) g_diag[grow] = f.y * INV_TEMP;
                }
            }

#pragma unroll
    for (int mi = 0; mi < 4; mi++)
#pragma unroll
        for (int g = 0; g < 2; g++) {
            float v = rs[mi][g];
            v += __shfl_xor_sync(0xffffffffu, v, 1);
            v += __shfl_xor_sync(0xffffffffu, v, 2);
            if ((lane & 3) == 0) {
                int grow = rowBase + wm * 64 + mi * 16 + g * 8 + (lane >> 2);
                atomicAdd(&g_S[grow], v);
            }
        }
}

// ---------------------------------------------------------------------------
// Kernel 3: loss = mean_i( M + log(S_i) - diag_i ), fast FMA-pipe log.
// ---------------------------------------------------------------------------
__global__ void finalize_kernel(float* __restrict__ out) {
    __shared__ float red[32];
    float local = 0.0f;
    for (int i = threadIdx.x; i < NROWS; i += blockDim.x)
        local += INV_TEMP + fast_log(g_S[i]) - g_diag[i];

    int lane = threadIdx.x & 31;
    int warp = threadIdx.x >> 5;
#pragma unroll
    for (int o = 16; o; o >>= 1) local += __shfl_xor_sync(0xffffffffu, local, o);
    if (lane == 0) red[warp] = local;
    __syncthreads();
    if (threadIdx.x < 32) {
        float v = (threadIdx.x < (blockDim.x >> 5)) ? red[threadIdx.x] : 0.0f;
#pragma unroll
        for (int o = 16; o; o >>= 1) v += __shfl_xor_sync(0xffffffffu, v, o);
        if (threadIdx.x == 0) out[0] = v / (float)NROWS;
    }
}

// ---------------------------------------------------------------------------
extern "C" void kernel_launch(void* const* d_in, const int* in_sizes, int n_in,
                              void* d_out, int out_size) {
    const float* q = (const float*)d_in[0];
    const float* k = (const float*)d_in[1];
    (void)in_sizes; (void)n_in; (void)out_size;

    static int attr_set = 0;
    if (!attr_set) {
        cudaFuncSetAttribute(gemm_lse_mma,
                             cudaFuncAttributeMaxDynamicSharedMemorySize, SMEM_TOTAL);
        attr_set = 1;
    }

    normalize_kernel<<<dim3(NROWS / 16, 2), 256>>>(q, k);
    gemm_lse_mma<<<dim3(NROWS / BN, NROWS / BM), 256, SMEM_TOTAL>>>();
    finalize_kernel<<<1, 1024>>>((float*)d_out);
}

// round 16
// speedup vs baseline: 1.0770x; 1.0770x over previous
#include <cuda_runtime.h>
#include <cuda_fp16.h>
#include <cstdint>
#include <math.h>

#define NROWS 16384
#define DDIM  256
#define INV_TEMP 14.285714285714286f
#define KCA 20.609640474436812f   /* (1/0.07)*log2(e) */
#define LN2 0.6931471805599453f

#define BMT 128
#define BNT 128
#define BK  64
#define STG_BYTES 32768           /* (128+128) rows x 128B */
#define NSTAGE 3
#define SMEM_TOTAL (NSTAGE * STG_BYTES)   /* 96 KB */

// ---------------------------------------------------------------------------
// Scratch (no allocations allowed)
// ---------------------------------------------------------------------------
__device__ __half g_qn[NROWS * DDIM];
__device__ __half g_kn[NROWS * DDIM];
__device__ float g_S[NROWS];
__device__ float g_diag[NROWS];

// ---------------------------------------------------------------------------
// PTX helpers (base ISA only: compiles at target sm_103)
// ---------------------------------------------------------------------------
__device__ __forceinline__ uint32_t smem_u32(const void* p) {
    uint32_t a;
    asm("{ .reg .u64 t; cvta.to.shared.u64 t, %1; cvt.u32.u64 %0, t; }" : "=r"(a) : "l"(p));
    return a;
}
__device__ __forceinline__ void ldsm_x4(uint32_t* r, uint32_t addr) {
    asm volatile("ldmatrix.sync.aligned.m8n8.x4.shared.b16 {%0,%1,%2,%3}, [%4];"
                 : "=r"(r[0]), "=r"(r[1]), "=r"(r[2]), "=r"(r[3]) : "r"(addr));
}
// fp16-accumulate HMMA: D(2xb32 packed half2) = A(4) * B(2) + D
__device__ __forceinline__ void mma_16816_f16(uint32_t* d, const uint32_t* a, const uint32_t* b) {
    asm volatile("mma.sync.aligned.m16n8k16.row.col.f16.f16.f16.f16 "
                 "{%0,%1}, {%2,%3,%4,%5}, {%6,%7}, {%0,%1};"
                 : "+r"(d[0]), "+r"(d[1])
                 : "r"(a[0]), "r"(a[1]), "r"(a[2]), "r"(a[3]), "r"(b[0]), "r"(b[1]));
}
#define CP_ASYNC16(dst, src) \
    asm volatile("cp.async.cg.shared.global [%0], [%1], 16;" :: "r"(dst), "l"(src) : "memory")
#define CP_COMMIT() asm volatile("cp.async.commit_group;" ::: "memory")
#define CP_WAIT1()  asm volatile("cp.async.wait_group 1;" ::: "memory")

// Fast exp2 on the FMA/ALU pipes (avoids MUFU rt=8). x in [-42, 0.3] here.
__device__ __forceinline__ float fast_exp2(float x) {
    float r = x + 12582912.0f;
    float n = r - 12582912.0f;
    float f = x - n;
    int   e = __float_as_int(r) - 0x4B400000;
    float p = fmaf(f, 0.0096181291f, 0.0555041086f);
    p = fmaf(f, p, 0.2402265069f);
    p = fmaf(f, p, 0.6931471806f);
    p = fmaf(f, p, 1.0f);
    return p * __int_as_float((127 + e) << 23);
}

// Fast natural log on FMA/ALU pipes (S_i values here are modest positives).
__device__ __forceinline__ float fast_log(float x) {
    int   xi = __float_as_int(x);
    int   e  = ((xi - 0x3F2AAAAB) >> 23);            // exponent rel. to 2/3
    float m  = __int_as_float(xi - (e << 23));       // in [2/3, 4/3)
    float t  = (m - 1.0f) / (m + 1.0f);              // |t| <= 0.2
    float t2 = t * t;
    float p  = fmaf(t2, 0.1133157f, 0.1332887f);
    p = fmaf(t2, p, 0.2000003f);
    p = fmaf(t2, p, 0.3333333f);
    float lnm = t * fmaf(t2, p * 2.0f, 2.0f);
    return fmaf((float)e, LN2, lnm);
}

// ---------------------------------------------------------------------------
// Kernel 1: L2 normalize fp32 -> fp16. FOUR rows per warp, all 8 float4
// loads issued before any reduction (MLP 8/thread). Zeroes g_S.
// ---------------------------------------------------------------------------
__global__ void normalize_kernel(const float* __restrict__ q,
                                 const float* __restrict__ k) {
    int warp = threadIdx.x >> 5;
    int lane = threadIdx.x & 31;
    int row0 = (blockIdx.x * (blockDim.x >> 5) + warp) * 4;
    if (row0 >= NROWS) return;

    const float* src = (blockIdx.y == 0) ? q : k;
    __half*      dst = (blockIdx.y == 0) ? g_qn : g_kn;

    float4 v[4][2];
#pragma unroll
    for (int r = 0; r < 4; r++) {
        const float4* p4 = reinterpret_cast<const float4*>(src + (size_t)(row0 + r) * DDIM);
        v[r][0] = p4[2 * lane];
        v[r][1] = p4[2 * lane + 1];
    }

    float s[4];
#pragma unroll
    for (int r = 0; r < 4; r++) {
        s[r] = v[r][0].x * v[r][0].x + v[r][0].y * v[r][0].y
             + v[r][0].z * v[r][0].z + v[r][0].w * v[r][0].w
             + v[r][1].x * v[r][1].x + v[r][1].y * v[r][1].y
             + v[r][1].z * v[r][1].z + v[r][1].w * v[r][1].w;
    }
#pragma unroll
    for (int o = 16; o; o >>= 1) {
#pragma unroll
        for (int r = 0; r < 4; r++) s[r] += __shfl_xor_sync(0xffffffffu, s[r], o);
    }

#pragma unroll
    for (int r = 0; r < 4; r++) {
        float inv = 1.0f / fmaxf(sqrtf(s[r]), 1e-12f);
        __half2 h[4];
        h[0] = __floats2half2_rn(v[r][0].x * inv, v[r][0].y * inv);
        h[1] = __floats2half2_rn(v[r][0].z * inv, v[r][0].w * inv);
        h[2] = __floats2half2_rn(v[r][1].x * inv, v[r][1].y * inv);
        h[3] = __floats2half2_rn(v[r][1].z * inv, v[r][1].w * inv);
        *reinterpret_cast<uint4*>(dst + (size_t)(row0 + r) * DDIM + lane * 8) =
            *reinterpret_cast<uint4*>(h);
    }

    if (blockIdx.y == 0 && lane < 4) g_S[row0 + lane] = 0.0f;
}

// ---------------------------------------------------------------------------
// Kernel 2: fp16 mma.sync GEMM (qn @ kn^T) fused with exp-sum epilogue.
// R12/R14 champion — saturates the legacy tensor pipe (~700 MAC/cyc/SM =
// HMMA.16816 rt~12 ceiling): CTA 128x128, 128 threads, 4 warps (2m x 2n)
// each 64x64 with fp16 packed-half2 accumulators; BK=64, 3 stages, 4
// barrier-free k16 slices per iteration, occ 2.
// ---------------------------------------------------------------------------
__global__ void __launch_bounds__(128, 2) gemm_lse_mma() {
    extern __shared__ __align__(1024) char smem[];
    const uint32_t sb = smem_u32(smem);

    const int tid  = threadIdx.x;
    const int lane = tid & 31;
    const int wid  = tid >> 5;
    const int wm   = wid >> 1;      // 0..1 -> 64-row slice
    const int wn   = wid & 1;       // 0..1 -> 64-col slice
    const int bx   = blockIdx.x;
    const int by   = blockIdx.y;
    const int rowBase = by * BMT;
    const int colBase = bx * BNT;

    // --- swizzled ldmatrix offsets for k-slice 0 (slice s: XOR s<<5) ---
    uint32_t offA[4], offB[4];
#pragma unroll
    for (int mi = 0; mi < 4; mi++) {
        int r = wm * 64 + mi * 16 + (lane & 15);
        int c = lane >> 4;
        offA[mi] = r * 128 + ((c ^ (r & 7)) << 4);
    }
#pragma unroll
    for (int ni = 0; ni < 4; ni++) {
        int r = BMT + wn * 64 + ni * 16 + (lane & 7) + ((lane >> 4) << 3);
        int c = (lane >> 3) & 1;
        offB[ni] = r * 128 + ((c ^ (r & 7)) << 4);
    }

    // --- stage loader: 16 x 16B chunks per thread (256 rows x 8 chunks) ---
    auto load_stage = [&](int kb, int s) {
#pragma unroll
        for (int h = 0; h < 16; h++) {
            int j = tid + h * 128;          // 0..2047
            int r = j >> 3, c = j & 7;
            uint32_t dst = sb + s * STG_BYTES + r * 128 + ((c ^ (r & 7)) << 4);
            const __half* src = (r < BMT)
                ? g_qn + (size_t)(rowBase + r) * DDIM + kb * BK + c * 8
                : g_kn + (size_t)(colBase + (r - BMT)) * DDIM + kb * BK + c * 8;
            CP_ASYNC16(dst, src);
        }
        CP_COMMIT();
    };

    uint32_t acc[4][8][2];          // packed half2: [mi][ni8][row-group]
#pragma unroll
    for (int mi = 0; mi < 4; mi++)
#pragma unroll
        for (int ni = 0; ni < 8; ni++) { acc[mi][ni][0] = 0u; acc[mi][ni][1] = 0u; }

    load_stage(0, 0);
    load_stage(1, 1);

#pragma unroll
    for (int kb = 0; kb < 4; kb++) {
        CP_WAIT1();
        __syncthreads();                    // stage kb ready; kb-1 reads done
        if (kb + 2 < 4) load_stage(kb + 2, (kb + 2) % NSTAGE);
        else            CP_COMMIT();        // keep wait_group count exact

        const uint32_t stg = sb + (kb % NSTAGE) * STG_BYTES;
#pragma unroll
        for (int s = 0; s < 4; s++) {       // 4 barrier-free k16 slices
            const uint32_t kx = (uint32_t)(s << 5);
            uint32_t af[4][4], bf[4][4];
#pragma unroll
            for (int mi = 0; mi < 4; mi++) ldsm_x4(af[mi], (stg + offA[mi]) ^ kx);
#pragma unroll
            for (int ni = 0; ni < 4; ni++) ldsm_x4(bf[ni], (stg + offB[ni]) ^ kx);
#pragma unroll
            for (int mi = 0; mi < 4; mi++)
#pragma unroll
                for (int ni = 0; ni < 4; ni++) {
                    mma_16816_f16(acc[mi][ni * 2 + 0], af[mi], &bf[ni][0]);
                    mma_16816_f16(acc[mi][ni * 2 + 1], af[mi], &bf[ni][2]);
                }
        }
    }

    // --- fused epilogue: exp2 row-sums + diag capture ---
    float rs[4][2];
#pragma unroll
    for (int mi = 0; mi < 4; mi++) { rs[mi][0] = 0.0f; rs[mi][1] = 0.0f; }
    const bool diagblk = (bx == by);
#pragma unroll
    for (int mi = 0; mi < 4; mi++)
#pragma unroll
        for (int ni = 0; ni < 8; ni++)
#pragma unroll
            for (int g = 0; g < 2; g++) {
                float2 f = __half22float2(*reinterpret_cast<__half2*>(&acc[mi][ni][g]));
                rs[mi][g] += fast_exp2(fmaf(f.x, KCA, -KCA));
                rs[mi][g] += fast_exp2(fmaf(f.y, KCA, -KCA));
                if (diagblk) {
                    int grow = rowBase + wm * 64 + mi * 16 + g * 8 + (lane >> 2);
                    int gcol = colBase + wn * 64 + ni * 8 + ((lane & 3) << 1);
                    if (grow == gcol)     g_diag[grow] = f.x * INV_TEMP;
                    if (grow == gcol + 1) g_diag[grow] = f.y * INV_TEMP;
                }
            }

#pragma unroll
    for (int mi = 0; mi < 4; mi++)
#pragma unroll
        for (int g = 0; g < 2; g++) {
            float v = rs[mi][g];
            v += __shfl_xor_sync(0xffffffffu, v, 1);
            v += __shfl_xor_sync(0xffffffffu, v, 2);
            if ((lane & 3) == 0) {
                int grow = rowBase + wm * 64 + mi * 16 + g * 8 + (lane >> 2);
                atomicAdd(&g_S[grow], v);
            }
        }
}

// ---------------------------------------------------------------------------
// Kernel 3: loss = mean_i( M + log(S_i) - diag_i ), fast FMA-pipe log.
// ---------------------------------------------------------------------------
__global__ void finalize_kernel(float* __restrict__ out) {
    __shared__ float red[32];
    float local = 0.0f;
    for (int i = threadIdx.x; i < NROWS; i += blockDim.x)
        local += INV_TEMP + fast_log(g_S[i]) - g_diag[i];

    int lane = threadIdx.x & 31;
    int warp = threadIdx.x >> 5;
#pragma unroll
    for (int o = 16; o; o >>= 1) local += __shfl_xor_sync(0xffffffffu, local, o);
    if (lane == 0) red[warp] = local;
    __syncthreads();
    if (threadIdx.x < 32) {
        float v = (threadIdx.x < (blockDim.x >> 5)) ? red[threadIdx.x] : 0.0f;
#pragma unroll
        for (int o = 16; o; o >>= 1) v += __shfl_xor_sync(0xffffffffu, v, o);
        if (threadIdx.x == 0) out[0] = v / (float)NROWS;
    }
}

// ---------------------------------------------------------------------------
extern "C" void kernel_launch(void* const* d_in, const int* in_sizes, int n_in,
                              void* d_out, int out_size) {
    const float* q = (const float*)d_in[0];
    const float* k = (const float*)d_in[1];
    (void)in_sizes; (void)n_in; (void)out_size;

    static int attr_set = 0;
    if (!attr_set) {
        cudaFuncSetAttribute(gemm_lse_mma,
                             cudaFuncAttributeMaxDynamicSharedMemorySize, SMEM_TOTAL);
        attr_set = 1;
    }

    normalize_kernel<<<dim3(NROWS / 32, 2), 256>>>(q, k);
    gemm_lse_mma<<<dim3(NROWS / BNT, NROWS / BMT), 128, SMEM_TOTAL>>>();
    finalize_kernel<<<1, 1024>>>((float*)d_out);
}

// round 17
// speedup vs baseline: 1.0794x; 1.0023x over previous
#include <cuda_runtime.h>
#include <cuda_fp16.h>
#include <cstdint>
#include <math.h>

#define NROWS 16384
#define DDIM  256
#define INV_TEMP 14.285714285714286f
#define KCA 20.609640474436812f   /* (1/0.07)*log2(e) */
#define LN2 0.6931471805599453f

#define BMT 128
#define BNT 128
#define BK  64
#define STG_BYTES 32768           /* (128+128) rows x 128B */
#define NSTAGE 3
#define SMEM_TOTAL (NSTAGE * STG_BYTES)   /* 96 KB */

// ---------------------------------------------------------------------------
// Scratch (no allocations allowed)
// ---------------------------------------------------------------------------
__device__ __half g_qn[NROWS * DDIM];
__device__ __half g_kn[NROWS * DDIM];
__device__ float g_S[NROWS];
__device__ float g_diag[NROWS];

// ---------------------------------------------------------------------------
// PTX helpers (base ISA only: compiles at target sm_103)
// ---------------------------------------------------------------------------
__device__ __forceinline__ uint32_t smem_u32(const void* p) {
    uint32_t a;
    asm("{ .reg .u64 t; cvta.to.shared.u64 t, %1; cvt.u32.u64 %0, t; }" : "=r"(a) : "l"(p));
    return a;
}
__device__ __forceinline__ void ldsm_x4(uint32_t* r, uint32_t addr) {
    asm volatile("ldmatrix.sync.aligned.m8n8.x4.shared.b16 {%0,%1,%2,%3}, [%4];"
                 : "=r"(r[0]), "=r"(r[1]), "=r"(r[2]), "=r"(r[3]) : "r"(addr));
}
// fp16-accumulate HMMA: D(2xb32 packed half2) = A(4) * B(2) + D
__device__ __forceinline__ void mma_16816_f16(uint32_t* d, const uint32_t* a, const uint32_t* b) {
    asm volatile("mma.sync.aligned.m16n8k16.row.col.f16.f16.f16.f16 "
                 "{%0,%1}, {%2,%3,%4,%5}, {%6,%7}, {%0,%1};"
                 : "+r"(d[0]), "+r"(d[1])
                 : "r"(a[0]), "r"(a[1]), "r"(a[2]), "r"(a[3]), "r"(b[0]), "r"(b[1]));
}
#define CP_ASYNC16(dst, src) \
    asm volatile("cp.async.cg.shared.global [%0], [%1], 16;" :: "r"(dst), "l"(src) : "memory")
#define CP_COMMIT() asm volatile("cp.async.commit_group;" ::: "memory")
#define CP_WAIT1()  asm volatile("cp.async.wait_group 1;" ::: "memory")

// Fast exp2 on the FMA/ALU pipes (avoids MUFU rt=8). x in [-42, 0.3] here.
__device__ __forceinline__ float fast_exp2(float x) {
    float r = x + 12582912.0f;
    float n = r - 12582912.0f;
    float f = x - n;
    int   e = __float_as_int(r) - 0x4B400000;
    float p = fmaf(f, 0.0096181291f, 0.0555041086f);
    p = fmaf(f, p, 0.2402265069f);
    p = fmaf(f, p, 0.6931471806f);
    p = fmaf(f, p, 1.0f);
    return p * __int_as_float((127 + e) << 23);
}

// Fast natural log on FMA/ALU pipes (S_i values here are modest positives).
__device__ __forceinline__ float fast_log(float x) {
    int   xi = __float_as_int(x);
    int   e  = ((xi - 0x3F2AAAAB) >> 23);            // exponent rel. to 2/3
    float m  = __int_as_float(xi - (e << 23));       // in [2/3, 4/3)
    float t  = (m - 1.0f) / (m + 1.0f);              // |t| <= 0.2
    float t2 = t * t;
    float p  = fmaf(t2, 0.1133157f, 0.1332887f);
    p = fmaf(t2, p, 0.2000003f);
    p = fmaf(t2, p, 0.3333333f);
    float lnm = t * fmaf(t2, p * 2.0f, 2.0f);
    return fmaf((float)e, LN2, lnm);
}

// ---------------------------------------------------------------------------
// Kernel 1: L2 normalize fp32 -> fp16. Two rows per warp; zeroes g_S.
// ---------------------------------------------------------------------------
__global__ void normalize_kernel(const float* __restrict__ q,
                                 const float* __restrict__ k) {
    int warp = threadIdx.x >> 5;
    int lane = threadIdx.x & 31;
    int row0 = (blockIdx.x * (blockDim.x >> 5) + warp) * 2;
    if (row0 >= NROWS) return;

    const float* src = (blockIdx.y == 0) ? q : k;
    __half*      dst = (blockIdx.y == 0) ? g_qn : g_kn;

    const float4* a4 = reinterpret_cast<const float4*>(src + (size_t)row0 * DDIM);
    const float4* b4 = reinterpret_cast<const float4*>(src + (size_t)(row0 + 1) * DDIM);
    float4 a0 = a4[2 * lane], a1 = a4[2 * lane + 1];
    float4 b0 = b4[2 * lane], b1 = b4[2 * lane + 1];

    float sa = a0.x * a0.x + a0.y * a0.y + a0.z * a0.z + a0.w * a0.w
             + a1.x * a1.x + a1.y * a1.y + a1.z * a1.z + a1.w * a1.w;
    float sb = b0.x * b0.x + b0.y * b0.y + b0.z * b0.z + b0.w * b0.w
             + b1.x * b1.x + b1.y * b1.y + b1.z * b1.z + b1.w * b1.w;
#pragma unroll
    for (int o = 16; o; o >>= 1) {
        sa += __shfl_xor_sync(0xffffffffu, sa, o);
        sb += __shfl_xor_sync(0xffffffffu, sb, o);
    }
    float ia = 1.0f / fmaxf(sqrtf(sa), 1e-12f);
    float ib = 1.0f / fmaxf(sqrtf(sb), 1e-12f);

    __half2 h[4];
    h[0] = __floats2half2_rn(a0.x * ia, a0.y * ia);
    h[1] = __floats2half2_rn(a0.z * ia, a0.w * ia);
    h[2] = __floats2half2_rn(a1.x * ia, a1.y * ia);
    h[3] = __floats2half2_rn(a1.z * ia, a1.w * ia);
    *reinterpret_cast<uint4*>(dst + (size_t)row0 * DDIM + lane * 8) =
        *reinterpret_cast<uint4*>(h);
    h[0] = __floats2half2_rn(b0.x * ib, b0.y * ib);
    h[1] = __floats2half2_rn(b0.z * ib, b0.w * ib);
    h[2] = __floats2half2_rn(b1.x * ib, b1.y * ib);
    h[3] = __floats2half2_rn(b1.z * ib, b1.w * ib);
    *reinterpret_cast<uint4*>(dst + (size_t)(row0 + 1) * DDIM + lane * 8) =
        *reinterpret_cast<uint4*>(h);

    if (blockIdx.y == 0 && lane < 2) g_S[row0 + lane] = 0.0f;
}

// ---------------------------------------------------------------------------
// Kernel 2: fp16 mma.sync GEMM (qn @ kn^T) fused with exp-sum epilogue.
// R12/R14 champion — saturates the legacy tensor pipe (~700 MAC/cyc/SM):
// CTA 128x128, 128 threads, 4 warps (2m x 2n) each 64x64 with fp16
// packed-half2 accumulators; BK=64, 3 stages (explicit ring counters),
// 4 barrier-free k16 slices per iteration, occ 2.
// ---------------------------------------------------------------------------
__global__ void __launch_bounds__(128, 2) gemm_lse_mma() {
    extern __shared__ __align__(1024) char smem[];
    const uint32_t sb = smem_u32(smem);

    const int tid  = threadIdx.x;
    const int lane = tid & 31;
    const int wid  = tid >> 5;
    const int wm   = wid >> 1;      // 0..1 -> 64-row slice
    const int wn   = wid & 1;       // 0..1 -> 64-col slice
    const int bx   = blockIdx.x;
    const int by   = blockIdx.y;
    const int rowBase = by * BMT;
    const int colBase = bx * BNT;

    // --- swizzled ldmatrix offsets for k-slice 0 (slice s: XOR s<<5) ---
    uint32_t offA[4], offB[4];
#pragma unroll
    for (int mi = 0; mi < 4; mi++) {
        int r = wm * 64 + mi * 16 + (lane & 15);
        int c = lane >> 4;
        offA[mi] = r * 128 + ((c ^ (r & 7)) << 4);
    }
#pragma unroll
    for (int ni = 0; ni < 4; ni++) {
        int r = BMT + wn * 64 + ni * 16 + (lane & 7) + ((lane >> 4) << 3);
        int c = (lane >> 3) & 1;
        offB[ni] = r * 128 + ((c ^ (r & 7)) << 4);
    }

    // --- stage loader: 16 x 16B chunks per thread (256 rows x 8 chunks) ---
    auto load_stage = [&](int kb, int s) {
#pragma unroll
        for (int h = 0; h < 16; h++) {
            int j = tid + h * 128;          // 0..2047
            int r = j >> 3, c = j & 7;
            uint32_t dst = sb + s * STG_BYTES + r * 128 + ((c ^ (r & 7)) << 4);
            const __half* src = (r < BMT)
                ? g_qn + (size_t)(rowBase + r) * DDIM + kb * BK + c * 8
                : g_kn + (size_t)(colBase + (r - BMT)) * DDIM + kb * BK + c * 8;
            CP_ASYNC16(dst, src);
        }
        CP_COMMIT();
    };

    uint32_t acc[4][8][2];          // packed half2: [mi][ni8][row-group]
#pragma unroll
    for (int mi = 0; mi < 4; mi++)
#pragma unroll
        for (int ni = 0; ni < 8; ni++) { acc[mi][ni][0] = 0u; acc[mi][ni][1] = 0u; }

    load_stage(0, 0);
    load_stage(1, 1);

    int st_c = 0;                   // stage being computed this iteration
    int st_l = 2;                   // stage receiving the prefetch
#pragma unroll
    for (int kb = 0; kb < 4; kb++) {
        CP_WAIT1();
        __syncthreads();                    // stage kb ready; kb-1 reads done
        if (kb + 2 < 4) load_stage(kb + 2, st_l);
        else            CP_COMMIT();        // keep wait_group count exact
        st_l = (st_l == 2) ? 0 : st_l + 1;

        const uint32_t stg = sb + st_c * STG_BYTES;
        st_c = (st_c == 2) ? 0 : st_c + 1;
#pragma unroll
        for (int s = 0; s < 4; s++) {       // 4 barrier-free k16 slices
            const uint32_t kx = (uint32_t)(s << 5);
            uint32_t af[4][4], bf[4][4];
#pragma unroll
            for (int mi = 0; mi < 4; mi++) ldsm_x4(af[mi], (stg + offA[mi]) ^ kx);
#pragma unroll
            for (int ni = 0; ni < 4; ni++) ldsm_x4(bf[ni], (stg + offB[ni]) ^ kx);
#pragma unroll
            for (int mi = 0; mi < 4; mi++)
#pragma unroll
                for (int ni = 0; ni < 4; ni++) {
                    mma_16816_f16(acc[mi][ni * 2 + 0], af[mi], &bf[ni][0]);
                    mma_16816_f16(acc[mi][ni * 2 + 1], af[mi], &bf[ni][2]);
                }
        }
    }

    // --- fused epilogue: exp2 row-sums + diag capture ---
    float rs[4][2];
#pragma unroll
    for (int mi = 0; mi < 4; mi++) { rs[mi][0] = 0.0f; rs[mi][1] = 0.0f; }
    const bool diagblk = (bx == by);
#pragma unroll
    for (int mi = 0; mi < 4; mi++)
#pragma unroll
        for (int ni = 0; ni < 8; ni++)
#pragma unroll
            for (int g = 0; g < 2; g++) {
                float2 f = __half22float2(*reinterpret_cast<__half2*>(&acc[mi][ni][g]));
                rs[mi][g] += fast_exp2(fmaf(f.x, KCA, -KCA));
                rs[mi][g] += fast_exp2(fmaf(f.y, KCA, -KCA));
                if (diagblk) {
                    int grow = rowBase + wm * 64 + mi * 16 + g * 8 + (lane >> 2);
                    int gcol = colBase + wn * 64 + ni * 8 + ((lane & 3) << 1);
                    if (grow == gcol)     g_diag[grow] = f.x * INV_TEMP;
                    if (grow == gcol + 1) g_diag[grow] = f.y * INV_TEMP;
                }
            }

#pragma unroll
    for (int mi = 0; mi < 4; mi++)
#pragma unroll
        for (int g = 0; g < 2; g++) {
            float v = rs[mi][g];
            v += __shfl_xor_sync(0xffffffffu, v, 1);
            v += __shfl_xor_sync(0xffffffffu, v, 2);
            if ((lane & 3) == 0) {
                int grow = rowBase + wm * 64 + mi * 16 + g * 8 + (lane >> 2);
                atomicAdd(&g_S[grow], v);
            }
        }
}

// ---------------------------------------------------------------------------
// Kernel 3: loss = mean_i( M + log(S_i) - diag_i ), fast FMA-pipe log.
// ---------------------------------------------------------------------------
__global__ void finalize_kernel(float* __restrict__ out) {
    __shared__ float red[32];
    float local = 0.0f;
    for (int i = threadIdx.x; i < NROWS; i += blockDim.x)
        local += INV_TEMP + fast_log(g_S[i]) - g_diag[i];

    int lane = threadIdx.x & 31;
    int warp = threadIdx.x >> 5;
#pragma unroll
    for (int o = 16; o; o >>= 1) local += __shfl_xor_sync(0xffffffffu, local, o);
    if (lane == 0) red[warp] = local;
    __syncthreads();
    if (threadIdx.x < 32) {
        float v = (threadIdx.x < (blockDim.x >> 5)) ? red[threadIdx.x] : 0.0f;
#pragma unroll
        for (int o = 16; o; o >>= 1) v += __shfl_xor_sync(0xffffffffu, v, o);
        if (threadIdx.x == 0) out[0] = v / (float)NROWS;
    }
}

// ---------------------------------------------------------------------------
extern "C" void kernel_launch(void* const* d_in, const int* in_sizes, int n_in,
                              void* d_out, int out_size) {
    const float* q = (const float*)d_in[0];
    const float* k = (const float*)d_in[1];
    (void)in_sizes; (void)n_in; (void)out_size;

    static int attr_set = 0;
    if (!attr_set) {
        cudaFuncSetAttribute(gemm_lse_mma,
                             cudaFuncAttributeMaxDynamicSharedMemorySize, SMEM_TOTAL);
        attr_set = 1;
    }

    normalize_kernel<<<dim3(NROWS / 16, 2), 256>>>(q, k);
    gemm_lse_mma<<<dim3(NROWS / BNT, NROWS / BMT), 128, SMEM_TOTAL>>>();
    finalize_kernel<<<1, 1024>>>((float*)d_out);
}